// round 7
// baseline (speedup 1.0000x reference)
#include <cuda_runtime.h>
#include <cuda_bf16.h>
#include <math.h>
#include <stdint.h>

#define B_   2
#define S_   2048
#define DM   1024
#define NH   16
#define DH   64
#define WIN  256
#define SCALEF 0.125f
#define MT   (B_*S_)

// ---------------- scratch (__device__ globals; no allocs allowed) ----------
__device__ __nv_bfloat16 g_xh[(size_t)MT * DM],  g_xl[(size_t)MT * DM];
__device__ __nv_bfloat16 g_wqT_h[(size_t)3*DM*DM], g_wqT_l[(size_t)3*DM*DM];
__device__ __nv_bfloat16 g_woT_h[(size_t)DM*DM],   g_woT_l[(size_t)DM*DM];
__device__ __nv_bfloat16 g_qkvh[(size_t)MT*3*DM], g_qkvl[(size_t)MT*3*DM];
__device__ __nv_bfloat16 g_ah[(size_t)MT*DM],  g_al[(size_t)MT*DM];

// ---------------- helpers ---------------------------------------------------
__device__ __forceinline__ uint32_t s2u(const void* p){
    uint32_t a;
    asm("{ .reg .u64 t; cvta.to.shared.u64 t, %1; cvt.u32.u64 %0, t; }":"=r"(a):"l"(p));
    return a;
}
__device__ __forceinline__ void cp16(uint32_t dst, const void* src){
    asm volatile("cp.async.cg.shared.global [%0], [%1], 16;"::"r"(dst),"l"(src));
}
__device__ __forceinline__ void ldsm_x4(uint32_t& r0,uint32_t& r1,uint32_t& r2,uint32_t& r3,uint32_t addr){
    asm volatile("ldmatrix.sync.aligned.m8n8.x4.shared.b16 {%0,%1,%2,%3}, [%4];"
        : "=r"(r0),"=r"(r1),"=r"(r2),"=r"(r3) : "r"(addr));
}
__device__ __forceinline__ void ldsm_x4t(uint32_t& r0,uint32_t& r1,uint32_t& r2,uint32_t& r3,uint32_t addr){
    asm volatile("ldmatrix.sync.aligned.m8n8.x4.trans.shared.b16 {%0,%1,%2,%3}, [%4];"
        : "=r"(r0),"=r"(r1),"=r"(r2),"=r"(r3) : "r"(addr));
}
__device__ __forceinline__ void mma16816(float* c, uint32_t a0,uint32_t a1,uint32_t a2,uint32_t a3,
                                         uint32_t b0,uint32_t b1){
    asm volatile("mma.sync.aligned.m16n8k16.row.col.f32.bf16.bf16.f32 "
        "{%0,%1,%2,%3}, {%4,%5,%6,%7}, {%8,%9}, {%0,%1,%2,%3};"
        : "+f"(c[0]),"+f"(c[1]),"+f"(c[2]),"+f"(c[3])
        : "r"(a0),"r"(a1),"r"(a2),"r"(a3),"r"(b0),"r"(b1));
}
__device__ __forceinline__ uint32_t packsplit(float x, float y, uint32_t& lo){
    __nv_bfloat16 hx = __float2bfloat16(x), hy = __float2bfloat16(y);
    __nv_bfloat16 lx = __float2bfloat16(x - __bfloat162float(hx));
    __nv_bfloat16 ly = __float2bfloat16(y - __bfloat162float(hy));
    lo = (uint32_t)__bfloat16_as_ushort(lx) | ((uint32_t)__bfloat16_as_ushort(ly)<<16);
    return (uint32_t)__bfloat16_as_ushort(hx) | ((uint32_t)__bfloat16_as_ushort(hy)<<16);
}

// ---------------- prep kernels ---------------------------------------------
__global__ __launch_bounds__(256) void fsplit(const float* __restrict__ in,
                                              __nv_bfloat16* __restrict__ hi,
                                              __nv_bfloat16* __restrict__ lo, int n)
{
    int i = (blockIdx.x*256 + threadIdx.x)*2;
    if (i >= n) return;
    float2 v = *(const float2*)(in + i);
    __nv_bfloat16 h0 = __float2bfloat16(v.x);
    __nv_bfloat16 h1 = __float2bfloat16(v.y);
    float l0 = v.x - __bfloat162float(h0);
    float l1 = v.y - __bfloat162float(h1);
    *(__nv_bfloat162*)(hi + i) = __halves2bfloat162(h0, h1);
    *(__nv_bfloat162*)(lo + i) = __halves2bfloat162(__float2bfloat16(l0), __float2bfloat16(l1));
}

// W [K,N] row-major -> transposed split Th/Tl [N,K] bf16
__global__ __launch_bounds__(256) void tsplit(const float* __restrict__ W,
                                              __nv_bfloat16* __restrict__ Th,
                                              __nv_bfloat16* __restrict__ Tl, int K, int N)
{
    __shared__ float t[32][33];
    int n0 = blockIdx.x*32, k0 = blockIdx.y*32;
    int tx = threadIdx.x & 31, ty = threadIdx.x >> 5;  // 32x8
#pragma unroll
    for (int i = 0; i < 32; i += 8)
        t[ty+i][tx] = W[(size_t)(k0+ty+i)*N + n0+tx];
    __syncthreads();
#pragma unroll
    for (int i = 0; i < 32; i += 8){
        float v = t[tx][ty+i];
        __nv_bfloat16 h = __float2bfloat16(v);
        float lo = v - __bfloat162float(h);
        size_t o = (size_t)(n0+ty+i)*K + k0+tx;
        Th[o] = h; Tl[o] = __float2bfloat16(lo);
    }
}

// ---------------- bf16x3 HMMA GEMM ------------------------------------------
// C = Ah@Bh^T + Ah@Bl^T + Al@Bh^T.  Output: split bf16 (Ch,Cl) or fp32 (Cf).
// CTA tile 64x128, warp tile 32x32, 3-stage cp.async, ONE barrier per chunk.
#define BM 64
#define BN 128
#define BK 32
#define ROWB 80
#define OFF_AH 0
#define OFF_AL (BM*ROWB)
#define OFF_BH (2*BM*ROWB)
#define OFF_BL (2*BM*ROWB + BN*ROWB)
#define GSTAGE_BYTES (2*BM*ROWB + 2*BN*ROWB)   // 30720
#define GEMM_SMEM (3*GSTAGE_BYTES)             // 92160

__global__ __launch_bounds__(256, 2) void gemm_bf16x3(
    const __nv_bfloat16* __restrict__ Ah, const __nv_bfloat16* __restrict__ Al,
    const __nv_bfloat16* __restrict__ Bh, const __nv_bfloat16* __restrict__ Bl,
    __nv_bfloat16* __restrict__ Ch, __nv_bfloat16* __restrict__ Cl,
    float* __restrict__ Cf, int M, int N, int K)
{
    extern __shared__ char smraw[];
    const uint32_t sb = s2u(smraw);
    const int tid = threadIdx.x, lane = tid & 31, wid = tid >> 5;
    const int row0 = blockIdx.y * BM, col0 = blockIdx.x * BN;
    const int wm = (wid & 1) * 32;    // 2 warps in M
    const int wn = (wid >> 1) * 32;   // 4 warps in N
    const int nch = K / BK;

    const __nv_bfloat16* pAh = Ah + (size_t)row0 * K;
    const __nv_bfloat16* pAl = Al + (size_t)row0 * K;
    const __nv_bfloat16* pBh = Bh + (size_t)col0 * K;
    const __nv_bfloat16* pBl = Bl + (size_t)col0 * K;

    const int lr = tid >> 2;    // 0..63
    const int lq = tid & 3;     // 16B chunk in 64B row

    float acc[2][4][4];
#pragma unroll
    for (int f = 0; f < 2; f++)
#pragma unroll
        for (int j = 0; j < 4; j++)
#pragma unroll
            for (int i = 0; i < 4; i++) acc[f][j][i] = 0.f;

#define LOAD_STAGE(s_, c_)                                              \
    {                                                                   \
        uint32_t base_ = sb + (s_) * GSTAGE_BYTES;                      \
        size_t kof_ = (size_t)(c_) * BK;                                \
        uint32_t d_ = base_ + lr * ROWB + lq * 16;                      \
        size_t g_ = (size_t)lr * K + kof_ + lq * 8;                     \
        size_t g2_ = (size_t)(lr + 64) * K + kof_ + lq * 8;             \
        cp16(d_ + OFF_AH, pAh + g_);                                    \
        cp16(d_ + OFF_AL, pAl + g_);                                    \
        cp16(d_ + OFF_BH, pBh + g_);                                    \
        cp16(d_ + OFF_BL, pBl + g_);                                    \
        cp16(d_ + OFF_BH + 64*ROWB, pBh + g2_);                         \
        cp16(d_ + OFF_BL + 64*ROWB, pBl + g2_);                         \
    }

    // prologue: chunks 0, 1 in flight
    LOAD_STAGE(0, 0);
    asm volatile("cp.async.commit_group;");
    LOAD_STAGE(1, 1);
    asm volatile("cp.async.commit_group;");

    for (int c = 0; c < nch; c++){
        // group for chunk c must be complete; chunk c+1 may remain in flight
        asm volatile("cp.async.wait_group 1;");
        __syncthreads();   // single barrier per chunk

        // prefetch chunk c+2 (stage safe: last read at iter c-1, barrier proves done)
        if (c + 2 < nch){
            const int s2 = (c + 2) % 3;
            LOAD_STAGE(s2, c + 2);
        }
        asm volatile("cp.async.commit_group;");   // always commit (may be empty)

        const uint32_t base = sb + (c % 3) * GSTAGE_BYTES;
#pragma unroll
        for (int ks = 0; ks < 2; ks++){
            const uint32_t kcol = (ks * 16 + (lane >> 4) * 8) * 2;
            uint32_t ah[2][4], al[2][4], bh[2][4], bl[2][4];
#pragma unroll
            for (int f = 0; f < 2; f++){
                uint32_t ad = (wm + f * 16 + (lane & 15)) * ROWB + kcol;
                ldsm_x4(ah[f][0], ah[f][1], ah[f][2], ah[f][3], base + OFF_AH + ad);
                ldsm_x4(al[f][0], al[f][1], al[f][2], al[f][3], base + OFF_AL + ad);
            }
#pragma unroll
            for (int g = 0; g < 2; g++){
                uint32_t bd = (wn + g * 16 + (lane & 15)) * ROWB + kcol;
                ldsm_x4(bh[g][0], bh[g][1], bh[g][2], bh[g][3], base + OFF_BH + bd);
                ldsm_x4(bl[g][0], bl[g][1], bl[g][2], bl[g][3], base + OFF_BL + bd);
            }
#pragma unroll
            for (int f = 0; f < 2; f++)
#pragma unroll
                for (int j = 0; j < 4; j++){
                    const int g = j >> 1, o = j & 1;
                    mma16816(acc[f][j], ah[f][0], ah[f][1], ah[f][2], ah[f][3],
                             bh[g][o], bh[g][o + 2]);
                    mma16816(acc[f][j], ah[f][0], ah[f][1], ah[f][2], ah[f][3],
                             bl[g][o], bl[g][o + 2]);
                    mma16816(acc[f][j], al[f][0], al[f][1], al[f][2], al[f][3],
                             bh[g][o], bh[g][o + 2]);
                }
        }
    }

#pragma unroll
    for (int f = 0; f < 2; f++){
        const int row = row0 + wm + f * 16 + (lane >> 2);
#pragma unroll
        for (int j = 0; j < 4; j++){
            const int col = col0 + wn + j * 8 + (lane & 3) * 2;
            if (Cf){
                *(float2*)(Cf + (size_t)row * N + col)       = make_float2(acc[f][j][0], acc[f][j][1]);
                *(float2*)(Cf + (size_t)(row + 8) * N + col) = make_float2(acc[f][j][2], acc[f][j][3]);
            } else {
                uint32_t lo0, hi0, lo1, hi1;
                hi0 = packsplit(acc[f][j][0], acc[f][j][1], lo0);
                hi1 = packsplit(acc[f][j][2], acc[f][j][3], lo1);
                *(uint32_t*)(Ch + (size_t)row * N + col)       = hi0;
                *(uint32_t*)(Cl + (size_t)row * N + col)       = lo0;
                *(uint32_t*)(Ch + (size_t)(row + 8) * N + col) = hi1;
                *(uint32_t*)(Cl + (size_t)(row + 8) * N + col) = lo1;
            }
        }
    }
}

// ---------------- HMMA sliding-window flash attention -----------------------
#define RWB 144
#define BQH 0
#define BQL (64*RWB)
#define BKH (2*64*RWB)
#define BKL (3*64*RWB)
#define BVH (4*64*RWB)
#define BVL (5*64*RWB)
#define ATTN_SMEM (6*64*RWB)

__global__ __launch_bounds__(128) void attn_hmma(
    const __nv_bfloat16* __restrict__ qh, const __nv_bfloat16* __restrict__ ql,
    __nv_bfloat16* __restrict__ oh, __nv_bfloat16* __restrict__ ol)
{
    extern __shared__ char smc[];
    const uint32_t sb = s2u(smc);
    const int tid = threadIdx.x, lane = tid & 31, wid = tid >> 5;
    const int qt = blockIdx.x, bhid = blockIdx.y;
    const int b = bhid >> 4, h = bhid & 15;
    const int qs = qt * 64;
    const int wm = wid * 16;
    const size_t tok0 = (size_t)b * S_;

    {
        const __nv_bfloat16* qbh = qh + (tok0 + qs) * 3072 + h * 64;
        const __nv_bfloat16* qbl = ql + (tok0 + qs) * 3072 + h * 64;
        for (int i = tid; i < 512; i += 128){
            int r = i >> 3, q = i & 7;
            *(uint4*)(smc + BQH + r*RWB + q*16) = *(const uint4*)(qbh + (size_t)r*3072 + q*8);
            *(uint4*)(smc + BQL + r*RWB + q*16) = *(const uint4*)(qbl + (size_t)r*3072 + q*8);
        }
    }
    __syncthreads();

    uint32_t aqh[4][4], aql[4][4];
#pragma unroll
    for (int ks = 0; ks < 4; ks++){
        uint32_t ad = (uint32_t)((wm + (lane & 15)) * RWB + (ks*16 + (lane >> 4)*8) * 2);
        ldsm_x4(aqh[ks][0], aqh[ks][1], aqh[ks][2], aqh[ks][3], sb + BQH + ad);
        ldsm_x4(aql[ks][0], aql[ks][1], aql[ks][2], aql[ks][3], sb + BQL + ad);
    }

    float oacc[8][4];
#pragma unroll
    for (int f = 0; f < 8; f++)
#pragma unroll
        for (int e = 0; e < 4; e++) oacc[f][e] = 0.f;
    float m0 = -1e30f, m1 = -1e30f, l0 = 0.f, l1 = 0.f;

    const int ilo = qs + wm + (lane >> 2);
    const int ihi = ilo + 8;

    const int js = qs - (WIN - 1);
    const int t0 = js > 0 ? (js >> 6) : 0;

    for (int kt = t0; kt <= qt; kt++){
        const int jb = kt * 64;
        __syncthreads();
        for (int i = tid; i < 512; i += 128){
            int r = i >> 3, q = i & 7;
            size_t g = (tok0 + jb + r) * 3072 + h*64 + q*8;
            uint32_t so = r*RWB + q*16;
            *(uint4*)(smc + BKH + so) = *(const uint4*)(qh + g + 1024);
            *(uint4*)(smc + BKL + so) = *(const uint4*)(ql + g + 1024);
            *(uint4*)(smc + BVH + so) = *(const uint4*)(qh + g + 2048);
            *(uint4*)(smc + BVL + so) = *(const uint4*)(ql + g + 2048);
        }
        __syncthreads();

        float sacc[8][4];
#pragma unroll
        for (int f = 0; f < 8; f++)
#pragma unroll
            for (int e = 0; e < 4; e++) sacc[f][e] = 0.f;

#pragma unroll
        for (int g = 0; g < 4; g++){
#pragma unroll
            for (int ks = 0; ks < 4; ks++){
                uint32_t bd = (uint32_t)((g*16 + (lane & 15)) * RWB + (ks*16 + (lane >> 4)*8) * 2);
                uint32_t kh0,kh1,kh2,kh3, kl0,kl1,kl2,kl3;
                ldsm_x4(kh0,kh1,kh2,kh3, sb + BKH + bd);
                ldsm_x4(kl0,kl1,kl2,kl3, sb + BKL + bd);
                mma16816(sacc[2*g],   aqh[ks][0],aqh[ks][1],aqh[ks][2],aqh[ks][3], kh0, kh2);
                mma16816(sacc[2*g],   aqh[ks][0],aqh[ks][1],aqh[ks][2],aqh[ks][3], kl0, kl2);
                mma16816(sacc[2*g],   aql[ks][0],aql[ks][1],aql[ks][2],aql[ks][3], kh0, kh2);
                mma16816(sacc[2*g+1], aqh[ks][0],aqh[ks][1],aqh[ks][2],aqh[ks][3], kh1, kh3);
                mma16816(sacc[2*g+1], aqh[ks][0],aqh[ks][1],aqh[ks][2],aqh[ks][3], kl1, kl3);
                mma16816(sacc[2*g+1], aql[ks][0],aql[ks][1],aql[ks][2],aql[ks][3], kh1, kh3);
            }
        }

        float mx0 = -1e30f, mx1 = -1e30f;
#pragma unroll
        for (int f = 0; f < 8; f++){
            int c0 = jb + f*8 + 2*(lane & 3);
            int c1 = c0 + 1;
            float s0 = sacc[f][0]*SCALEF, s1 = sacc[f][1]*SCALEF;
            float s2 = sacc[f][2]*SCALEF, s3 = sacc[f][3]*SCALEF;
            sacc[f][0] = (c0 <= ilo && c0 > ilo - WIN) ? s0 : -1e30f;
            sacc[f][1] = (c1 <= ilo && c1 > ilo - WIN) ? s1 : -1e30f;
            sacc[f][2] = (c0 <= ihi && c0 > ihi - WIN) ? s2 : -1e30f;
            sacc[f][3] = (c1 <= ihi && c1 > ihi - WIN) ? s3 : -1e30f;
            mx0 = fmaxf(mx0, fmaxf(sacc[f][0], sacc[f][1]));
            mx1 = fmaxf(mx1, fmaxf(sacc[f][2], sacc[f][3]));
        }
        mx0 = fmaxf(mx0, __shfl_xor_sync(0xffffffffu, mx0, 1));
        mx0 = fmaxf(mx0, __shfl_xor_sync(0xffffffffu, mx0, 2));
        mx1 = fmaxf(mx1, __shfl_xor_sync(0xffffffffu, mx1, 1));
        mx1 = fmaxf(mx1, __shfl_xor_sync(0xffffffffu, mx1, 2));
        float mn0 = fmaxf(m0, mx0), mn1 = fmaxf(m1, mx1);
        float rc0 = __expf(m0 - mn0), rc1 = __expf(m1 - mn1);
        float rs0 = 0.f, rs1 = 0.f;
#pragma unroll
        for (int f = 0; f < 8; f++){
            sacc[f][0] = __expf(sacc[f][0] - mn0);
            sacc[f][1] = __expf(sacc[f][1] - mn0);
            sacc[f][2] = __expf(sacc[f][2] - mn1);
            sacc[f][3] = __expf(sacc[f][3] - mn1);
            rs0 += sacc[f][0] + sacc[f][1];
            rs1 += sacc[f][2] + sacc[f][3];
        }
        rs0 += __shfl_xor_sync(0xffffffffu, rs0, 1);
        rs0 += __shfl_xor_sync(0xffffffffu, rs0, 2);
        rs1 += __shfl_xor_sync(0xffffffffu, rs1, 1);
        rs1 += __shfl_xor_sync(0xffffffffu, rs1, 2);
        l0 = l0 * rc0 + rs0;  l1 = l1 * rc1 + rs1;
        m0 = mn0;  m1 = mn1;
#pragma unroll
        for (int f = 0; f < 8; f++){
            oacc[f][0] *= rc0; oacc[f][1] *= rc0;
            oacc[f][2] *= rc1; oacc[f][3] *= rc1;
        }

#pragma unroll
        for (int kk = 0; kk < 4; kk++){
            uint32_t pah[4], pal[4];
            pah[0] = packsplit(sacc[2*kk][0],   sacc[2*kk][1],   pal[0]);
            pah[1] = packsplit(sacc[2*kk][2],   sacc[2*kk][3],   pal[1]);
            pah[2] = packsplit(sacc[2*kk+1][0], sacc[2*kk+1][1], pal[2]);
            pah[3] = packsplit(sacc[2*kk+1][2], sacc[2*kk+1][3], pal[3]);
#pragma unroll
            for (int j2 = 0; j2 < 4; j2++){
                uint32_t vd = (uint32_t)((kk*16 + ((lane >> 3) & 1)*8 + (lane & 7)) * RWB
                                         + (j2*16 + (lane >> 4)*8) * 2);
                uint32_t vh0,vh1,vh2,vh3, vl0,vl1,vl2,vl3;
                ldsm_x4t(vh0,vh1,vh2,vh3, sb + BVH + vd);
                ldsm_x4t(vl0,vl1,vl2,vl3, sb + BVL + vd);
                mma16816(oacc[2*j2],   pah[0],pah[1],pah[2],pah[3], vh0, vh1);
                mma16816(oacc[2*j2],   pah[0],pah[1],pah[2],pah[3], vl0, vl1);
                mma16816(oacc[2*j2],   pal[0],pal[1],pal[2],pal[3], vh0, vh1);
                mma16816(oacc[2*j2+1], pah[0],pah[1],pah[2],pah[3], vh2, vh3);
                mma16816(oacc[2*j2+1], pah[0],pah[1],pah[2],pah[3], vl2, vl3);
                mma16816(oacc[2*j2+1], pal[0],pal[1],pal[2],pal[3], vh2, vh3);
            }
        }
    }

    float il0 = 1.f / l0, il1 = 1.f / l1;
    const int col = h*64 + 2*(lane & 3);
    size_t rowlo = (tok0 + ilo) * DM;
    size_t rowhi = (tok0 + ihi) * DM;
#pragma unroll
    for (int f = 0; f < 8; f++){
        uint32_t lo0, hi0, lo1, hi1;
        hi0 = packsplit(oacc[f][0]*il0, oacc[f][1]*il0, lo0);
        hi1 = packsplit(oacc[f][2]*il1, oacc[f][3]*il1, lo1);
        *(uint32_t*)(oh + rowlo + col + f*8) = hi0;
        *(uint32_t*)(ol + rowlo + col + f*8) = lo0;
        *(uint32_t*)(oh + rowhi + col + f*8) = hi1;
        *(uint32_t*)(ol + rowhi + col + f*8) = lo1;
    }
}

// ---------------------------------------------------------------------------
extern "C" void kernel_launch(void* const* d_in, const int* in_sizes, int n_in,
                              void* d_out, int out_size)
{
    const float* x    = (const float*)d_in[0];
    const float* Wqkv = (const float*)d_in[1];
    const float* Wout = (const float*)d_in[2];
    float* out = (float*)d_out;

    __nv_bfloat16 *xh, *xl, *wqh, *wql, *woh, *wol, *qkvh, *qkvl, *ah, *al;
    cudaGetSymbolAddress((void**)&xh, g_xh);
    cudaGetSymbolAddress((void**)&xl, g_xl);
    cudaGetSymbolAddress((void**)&wqh, g_wqT_h);
    cudaGetSymbolAddress((void**)&wql, g_wqT_l);
    cudaGetSymbolAddress((void**)&woh, g_woT_h);
    cudaGetSymbolAddress((void**)&wol, g_woT_l);
    cudaGetSymbolAddress((void**)&qkvh, g_qkvh);
    cudaGetSymbolAddress((void**)&qkvl, g_qkvl);
    cudaGetSymbolAddress((void**)&ah, g_ah);
    cudaGetSymbolAddress((void**)&al, g_al);

    cudaFuncSetAttribute(gemm_bf16x3, cudaFuncAttributeMaxDynamicSharedMemorySize, GEMM_SMEM);
    cudaFuncSetAttribute(attn_hmma, cudaFuncAttributeMaxDynamicSharedMemorySize, ATTN_SMEM);

    fsplit<<<(MT*DM/2 + 255)/256, 256>>>(x, xh, xl, MT*DM);
    tsplit<<<dim3(3*DM/32, DM/32), 256>>>(Wqkv, wqh, wql, DM, 3*DM);
    tsplit<<<dim3(DM/32, DM/32), 256>>>(Wout, woh, wol, DM, DM);
    gemm_bf16x3<<<dim3(3*DM/BN, MT/BM), 256, GEMM_SMEM>>>(xh, xl, wqh, wql,
                                                          qkvh, qkvl, nullptr, MT, 3*DM, DM);
    attn_hmma<<<dim3(S_/64, B_*NH), 128, ATTN_SMEM>>>(qkvh, qkvl, ah, al);
    gemm_bf16x3<<<dim3(DM/BN, MT/BM), 256, GEMM_SMEM>>>(ah, al, woh, wol,
                                                        nullptr, nullptr, out, MT, DM, DM);
}

// round 8
// speedup vs baseline: 1.5327x; 1.5327x over previous
#include <cuda_runtime.h>
#include <cuda_fp16.h>
#include <math.h>
#include <stdint.h>

#define B_   2
#define S_   2048
#define DM   1024
#define NH   16
#define DH   64
#define WIN  256
#define SCALEF 0.125f
#define MT   (B_*S_)
#define LSCALE 2048.0f
#define INV_LSCALE (1.0f/2048.0f)

// ---------------- scratch (__device__ globals; no allocs allowed) ----------
__device__ __half g_xh[(size_t)MT * DM];
__device__ __half g_wqT_h[(size_t)3*DM*DM], g_wqT_l[(size_t)3*DM*DM];
__device__ __half g_woT_h[(size_t)DM*DM],   g_woT_l[(size_t)DM*DM];
__device__ __half g_qkvh[(size_t)MT*3*DM];
__device__ __half g_ah[(size_t)MT*DM];

// ---------------- helpers ---------------------------------------------------
__device__ __forceinline__ uint32_t s2u(const void* p){
    uint32_t a;
    asm("{ .reg .u64 t; cvta.to.shared.u64 t, %1; cvt.u32.u64 %0, t; }":"=r"(a):"l"(p));
    return a;
}
__device__ __forceinline__ void cp16(uint32_t dst, const void* src){
    asm volatile("cp.async.cg.shared.global [%0], [%1], 16;"::"r"(dst),"l"(src));
}
__device__ __forceinline__ void ldsm_x4(uint32_t& r0,uint32_t& r1,uint32_t& r2,uint32_t& r3,uint32_t addr){
    asm volatile("ldmatrix.sync.aligned.m8n8.x4.shared.b16 {%0,%1,%2,%3}, [%4];"
        : "=r"(r0),"=r"(r1),"=r"(r2),"=r"(r3) : "r"(addr));
}
__device__ __forceinline__ void ldsm_x4t(uint32_t& r0,uint32_t& r1,uint32_t& r2,uint32_t& r3,uint32_t addr){
    asm volatile("ldmatrix.sync.aligned.m8n8.x4.trans.shared.b16 {%0,%1,%2,%3}, [%4];"
        : "=r"(r0),"=r"(r1),"=r"(r2),"=r"(r3) : "r"(addr));
}
__device__ __forceinline__ void mma16816(float* c, uint32_t a0,uint32_t a1,uint32_t a2,uint32_t a3,
                                         uint32_t b0,uint32_t b1){
    asm volatile("mma.sync.aligned.m16n8k16.row.col.f32.f16.f16.f32 "
        "{%0,%1,%2,%3}, {%4,%5,%6,%7}, {%8,%9}, {%0,%1,%2,%3};"
        : "+f"(c[0]),"+f"(c[1]),"+f"(c[2]),"+f"(c[3])
        : "r"(a0),"r"(a1),"r"(a2),"r"(a3),"r"(b0),"r"(b1));
}
__device__ __forceinline__ uint32_t packh2(float x, float y){
    __half2 h = __floats2half2_rn(x, y);
    return *(uint32_t*)&h;
}

// ---------------- prep kernels ---------------------------------------------
__global__ __launch_bounds__(256) void fhalf(const float* __restrict__ in,
                                             __half* __restrict__ hi, int n)
{
    int i = (blockIdx.x*256 + threadIdx.x)*4;
    if (i >= n) return;
    float4 v = *(const float4*)(in + i);
    __half2 a = __floats2half2_rn(v.x, v.y);
    __half2 b = __floats2half2_rn(v.z, v.w);
    *(__half2*)(hi + i)     = a;
    *(__half2*)(hi + i + 2) = b;
}

// W [K,N] row-major -> transposed split Th [N,K], Tl [N,K] (lo * 2048), fp16
__global__ __launch_bounds__(256) void tsplit(const float* __restrict__ W,
                                              __half* __restrict__ Th,
                                              __half* __restrict__ Tl, int K, int N)
{
    __shared__ float t[32][33];
    int n0 = blockIdx.x*32, k0 = blockIdx.y*32;
    int tx = threadIdx.x & 31, ty = threadIdx.x >> 5;  // 32x8
#pragma unroll
    for (int i = 0; i < 32; i += 8)
        t[ty+i][tx] = W[(size_t)(k0+ty+i)*N + n0+tx];
    __syncthreads();
#pragma unroll
    for (int i = 0; i < 32; i += 8){
        float v = t[tx][ty+i];
        __half h = __float2half_rn(v);
        float lo = (v - __half2float(h)) * LSCALE;
        size_t o = (size_t)(n0+ty+i)*K + k0+tx;
        Th[o] = h; Tl[o] = __float2half_rn(lo);
    }
}

// ---------------- fp16x2 HMMA GEMM ------------------------------------------
// C = Ah@(Bh + Bl*2^-11)^T.  A [M,K] fp16 (hi), B split [N,K] fp16.
// Output: fp16 (Ch) or fp32 (Cf).  2 MMAs per fragment pair, dual accumulators.
#define BM 64
#define BN 128
#define BK 32
#define ROWB 80
#define OFF_AH 0
#define OFF_BH (BM*ROWB)
#define OFF_BL (BM*ROWB + BN*ROWB)
#define GSTAGE_BYTES (BM*ROWB + 2*BN*ROWB)   // 25600
#define GEMM_SMEM (3*GSTAGE_BYTES)           // 76800

__global__ __launch_bounds__(256, 2) void gemm_fp16x2(
    const __half* __restrict__ Ah,
    const __half* __restrict__ Bh, const __half* __restrict__ Bl,
    __half* __restrict__ Ch, float* __restrict__ Cf, int M, int N, int K)
{
    extern __shared__ char smraw[];
    const uint32_t sb = s2u(smraw);
    const int tid = threadIdx.x, lane = tid & 31, wid = tid >> 5;
    const int row0 = blockIdx.y * BM, col0 = blockIdx.x * BN;
    const int wm = (wid & 1) * 32;
    const int wn = (wid >> 1) * 32;
    const int nch = K / BK;

    const __half* pAh = Ah + (size_t)row0 * K;
    const __half* pBh = Bh + (size_t)col0 * K;
    const __half* pBl = Bl + (size_t)col0 * K;

    const int lr = tid >> 2;
    const int lq = tid & 3;

    float acc[2][4][4], acc2[2][4][4];
#pragma unroll
    for (int f = 0; f < 2; f++)
#pragma unroll
        for (int j = 0; j < 4; j++)
#pragma unroll
            for (int i = 0; i < 4; i++){ acc[f][j][i] = 0.f; acc2[f][j][i] = 0.f; }

#define LOAD_STAGE(s_, c_)                                              \
    {                                                                   \
        uint32_t base_ = sb + (s_) * GSTAGE_BYTES;                      \
        size_t kof_ = (size_t)(c_) * BK;                                \
        uint32_t d_ = base_ + lr * ROWB + lq * 16;                      \
        size_t g_ = (size_t)lr * K + kof_ + lq * 8;                     \
        size_t g2_ = (size_t)(lr + 64) * K + kof_ + lq * 8;             \
        cp16(d_ + OFF_AH, pAh + g_);                                    \
        cp16(d_ + OFF_BH, pBh + g_);                                    \
        cp16(d_ + OFF_BL, pBl + g_);                                    \
        cp16(d_ + OFF_BH + 64*ROWB, pBh + g2_);                         \
        cp16(d_ + OFF_BL + 64*ROWB, pBl + g2_);                         \
    }

    LOAD_STAGE(0, 0);
    asm volatile("cp.async.commit_group;");
    LOAD_STAGE(1, 1);
    asm volatile("cp.async.commit_group;");

    for (int c = 0; c < nch; c++){
        asm volatile("cp.async.wait_group 1;");
        __syncthreads();

        if (c + 2 < nch){
            const int s2 = (c + 2) % 3;
            LOAD_STAGE(s2, c + 2);
        }
        asm volatile("cp.async.commit_group;");

        const uint32_t base = sb + (c % 3) * GSTAGE_BYTES;
#pragma unroll
        for (int ks = 0; ks < 2; ks++){
            const uint32_t kcol = (ks * 16 + (lane >> 4) * 8) * 2;
            uint32_t a[2][4], bh[2][4], bl[2][4];
#pragma unroll
            for (int f = 0; f < 2; f++){
                uint32_t ad = (wm + f * 16 + (lane & 15)) * ROWB + kcol;
                ldsm_x4(a[f][0], a[f][1], a[f][2], a[f][3], base + OFF_AH + ad);
            }
#pragma unroll
            for (int g = 0; g < 2; g++){
                uint32_t bd = (wn + g * 16 + (lane & 15)) * ROWB + kcol;
                ldsm_x4(bh[g][0], bh[g][1], bh[g][2], bh[g][3], base + OFF_BH + bd);
                ldsm_x4(bl[g][0], bl[g][1], bl[g][2], bl[g][3], base + OFF_BL + bd);
            }
#pragma unroll
            for (int f = 0; f < 2; f++)
#pragma unroll
                for (int j = 0; j < 4; j++){
                    const int g = j >> 1, o = j & 1;
                    mma16816(acc[f][j],  a[f][0], a[f][1], a[f][2], a[f][3],
                             bh[g][o], bh[g][o + 2]);
                    mma16816(acc2[f][j], a[f][0], a[f][1], a[f][2], a[f][3],
                             bl[g][o], bl[g][o + 2]);
                }
        }
    }

#pragma unroll
    for (int f = 0; f < 2; f++){
        const int row = row0 + wm + f * 16 + (lane >> 2);
#pragma unroll
        for (int j = 0; j < 4; j++){
            const int col = col0 + wn + j * 8 + (lane & 3) * 2;
            float v0 = acc[f][j][0] + acc2[f][j][0]*INV_LSCALE;
            float v1 = acc[f][j][1] + acc2[f][j][1]*INV_LSCALE;
            float v2 = acc[f][j][2] + acc2[f][j][2]*INV_LSCALE;
            float v3 = acc[f][j][3] + acc2[f][j][3]*INV_LSCALE;
            if (Cf){
                *(float2*)(Cf + (size_t)row * N + col)       = make_float2(v0, v1);
                *(float2*)(Cf + (size_t)(row + 8) * N + col) = make_float2(v2, v3);
            } else {
                *(uint32_t*)(Ch + (size_t)row * N + col)       = packh2(v0, v1);
                *(uint32_t*)(Ch + (size_t)(row + 8) * N + col) = packh2(v2, v3);
            }
        }
    }
}

// ---------------- fp16 HMMA sliding-window flash attention -------------------
#define RWB 144
#define AQ 0
#define AK (64*RWB)
#define AV (2*64*RWB)
#define ATTN_SMEM (3*64*RWB)    // 27648

__global__ __launch_bounds__(128) void attn_hmma(
    const __half* __restrict__ qkv, __half* __restrict__ oh)
{
    extern __shared__ char smc[];
    const uint32_t sb = s2u(smc);
    const int tid = threadIdx.x, lane = tid & 31, wid = tid >> 5;
    const int qt = blockIdx.x, bhid = blockIdx.y;
    const int b = bhid >> 4, h = bhid & 15;
    const int qs = qt * 64;
    const int wm = wid * 16;
    const size_t tok0 = (size_t)b * S_;

    // ---- load Q tile ----
    {
        const __half* qb = qkv + (tok0 + qs) * 3072 + h * 64;
        for (int i = tid; i < 512; i += 128){
            int r = i >> 3, q = i & 7;
            *(uint4*)(smc + AQ + r*RWB + q*16) = *(const uint4*)(qb + (size_t)r*3072 + q*8);
        }
    }
    __syncthreads();

    uint32_t aq[4][4];
#pragma unroll
    for (int ks = 0; ks < 4; ks++){
        uint32_t ad = (uint32_t)((wm + (lane & 15)) * RWB + (ks*16 + (lane >> 4)*8) * 2);
        ldsm_x4(aq[ks][0], aq[ks][1], aq[ks][2], aq[ks][3], sb + AQ + ad);
    }

    float oacc[8][4];
#pragma unroll
    for (int f = 0; f < 8; f++)
#pragma unroll
        for (int e = 0; e < 4; e++) oacc[f][e] = 0.f;
    float m0 = -1e30f, m1 = -1e30f, l0 = 0.f, l1 = 0.f;

    const int ilo = qs + wm + (lane >> 2);
    const int ihi = ilo + 8;

    const int js = qs - (WIN - 1);
    const int t0 = js > 0 ? (js >> 6) : 0;

    for (int kt = t0; kt <= qt; kt++){
        const int jb = kt * 64;
        __syncthreads();
        for (int i = tid; i < 512; i += 128){
            int r = i >> 3, q = i & 7;
            size_t g = (tok0 + jb + r) * 3072 + h*64 + q*8;
            uint32_t so = r*RWB + q*16;
            *(uint4*)(smc + AK + so) = *(const uint4*)(qkv + g + 1024);
            *(uint4*)(smc + AV + so) = *(const uint4*)(qkv + g + 2048);
        }
        __syncthreads();

        float sacc[8][4];
#pragma unroll
        for (int f = 0; f < 8; f++)
#pragma unroll
            for (int e = 0; e < 4; e++) sacc[f][e] = 0.f;

#pragma unroll
        for (int g = 0; g < 4; g++){
#pragma unroll
            for (int ks = 0; ks < 4; ks++){
                uint32_t bd = (uint32_t)((g*16 + (lane & 15)) * RWB + (ks*16 + (lane >> 4)*8) * 2);
                uint32_t k0,k1,k2,k3;
                ldsm_x4(k0,k1,k2,k3, sb + AK + bd);
                mma16816(sacc[2*g],   aq[ks][0],aq[ks][1],aq[ks][2],aq[ks][3], k0, k2);
                mma16816(sacc[2*g+1], aq[ks][0],aq[ks][1],aq[ks][2],aq[ks][3], k1, k3);
            }
        }

        float mx0 = -1e30f, mx1 = -1e30f;
#pragma unroll
        for (int f = 0; f < 8; f++){
            int c0 = jb + f*8 + 2*(lane & 3);
            int c1 = c0 + 1;
            float s0 = sacc[f][0]*SCALEF, s1 = sacc[f][1]*SCALEF;
            float s2 = sacc[f][2]*SCALEF, s3 = sacc[f][3]*SCALEF;
            sacc[f][0] = (c0 <= ilo && c0 > ilo - WIN) ? s0 : -1e30f;
            sacc[f][1] = (c1 <= ilo && c1 > ilo - WIN) ? s1 : -1e30f;
            sacc[f][2] = (c0 <= ihi && c0 > ihi - WIN) ? s2 : -1e30f;
            sacc[f][3] = (c1 <= ihi && c1 > ihi - WIN) ? s3 : -1e30f;
            mx0 = fmaxf(mx0, fmaxf(sacc[f][0], sacc[f][1]));
            mx1 = fmaxf(mx1, fmaxf(sacc[f][2], sacc[f][3]));
        }
        mx0 = fmaxf(mx0, __shfl_xor_sync(0xffffffffu, mx0, 1));
        mx0 = fmaxf(mx0, __shfl_xor_sync(0xffffffffu, mx0, 2));
        mx1 = fmaxf(mx1, __shfl_xor_sync(0xffffffffu, mx1, 1));
        mx1 = fmaxf(mx1, __shfl_xor_sync(0xffffffffu, mx1, 2));
        float mn0 = fmaxf(m0, mx0), mn1 = fmaxf(m1, mx1);
        float rc0 = __expf(m0 - mn0), rc1 = __expf(m1 - mn1);
        float rs0 = 0.f, rs1 = 0.f;
#pragma unroll
        for (int f = 0; f < 8; f++){
            sacc[f][0] = __expf(sacc[f][0] - mn0);
            sacc[f][1] = __expf(sacc[f][1] - mn0);
            sacc[f][2] = __expf(sacc[f][2] - mn1);
            sacc[f][3] = __expf(sacc[f][3] - mn1);
            rs0 += sacc[f][0] + sacc[f][1];
            rs1 += sacc[f][2] + sacc[f][3];
        }
        rs0 += __shfl_xor_sync(0xffffffffu, rs0, 1);
        rs0 += __shfl_xor_sync(0xffffffffu, rs0, 2);
        rs1 += __shfl_xor_sync(0xffffffffu, rs1, 1);
        rs1 += __shfl_xor_sync(0xffffffffu, rs1, 2);
        l0 = l0 * rc0 + rs0;  l1 = l1 * rc1 + rs1;
        m0 = mn0;  m1 = mn1;
#pragma unroll
        for (int f = 0; f < 8; f++){
            oacc[f][0] *= rc0; oacc[f][1] *= rc0;
            oacc[f][2] *= rc1; oacc[f][3] *= rc1;
        }

#pragma unroll
        for (int kk = 0; kk < 4; kk++){
            uint32_t pa[4];
            pa[0] = packh2(sacc[2*kk][0],   sacc[2*kk][1]);
            pa[1] = packh2(sacc[2*kk][2],   sacc[2*kk][3]);
            pa[2] = packh2(sacc[2*kk+1][0], sacc[2*kk+1][1]);
            pa[3] = packh2(sacc[2*kk+1][2], sacc[2*kk+1][3]);
#pragma unroll
            for (int j2 = 0; j2 < 4; j2++){
                uint32_t vd = (uint32_t)((kk*16 + ((lane >> 3) & 1)*8 + (lane & 7)) * RWB
                                         + (j2*16 + (lane >> 4)*8) * 2);
                uint32_t v0,v1,v2,v3;
                ldsm_x4t(v0,v1,v2,v3, sb + AV + vd);
                mma16816(oacc[2*j2],   pa[0],pa[1],pa[2],pa[3], v0, v1);
                mma16816(oacc[2*j2+1], pa[0],pa[1],pa[2],pa[3], v2, v3);
            }
        }
    }

    float il0 = 1.f / l0, il1 = 1.f / l1;
    const int col = h*64 + 2*(lane & 3);
    size_t rowlo = (tok0 + ilo) * DM;
    size_t rowhi = (tok0 + ihi) * DM;
#pragma unroll
    for (int f = 0; f < 8; f++){
        *(uint32_t*)(oh + rowlo + col + f*8) = packh2(oacc[f][0]*il0, oacc[f][1]*il0);
        *(uint32_t*)(oh + rowhi + col + f*8) = packh2(oacc[f][2]*il1, oacc[f][3]*il1);
    }
}

// ---------------------------------------------------------------------------
extern "C" void kernel_launch(void* const* d_in, const int* in_sizes, int n_in,
                              void* d_out, int out_size)
{
    const float* x    = (const float*)d_in[0];
    const float* Wqkv = (const float*)d_in[1];
    const float* Wout = (const float*)d_in[2];
    float* out = (float*)d_out;

    __half *xh, *wqh, *wql, *woh, *wol, *qkvh, *ah;
    cudaGetSymbolAddress((void**)&xh, g_xh);
    cudaGetSymbolAddress((void**)&wqh, g_wqT_h);
    cudaGetSymbolAddress((void**)&wql, g_wqT_l);
    cudaGetSymbolAddress((void**)&woh, g_woT_h);
    cudaGetSymbolAddress((void**)&wol, g_woT_l);
    cudaGetSymbolAddress((void**)&qkvh, g_qkvh);
    cudaGetSymbolAddress((void**)&ah, g_ah);

    cudaFuncSetAttribute(gemm_fp16x2, cudaFuncAttributeMaxDynamicSharedMemorySize, GEMM_SMEM);
    cudaFuncSetAttribute(attn_hmma, cudaFuncAttributeMaxDynamicSharedMemorySize, ATTN_SMEM);

    fhalf<<<(MT*DM/4 + 255)/256, 256>>>(x, xh, MT*DM);
    tsplit<<<dim3(3*DM/32, DM/32), 256>>>(Wqkv, wqh, wql, DM, 3*DM);
    tsplit<<<dim3(DM/32, DM/32), 256>>>(Wout, woh, wol, DM, DM);
    gemm_fp16x2<<<dim3(3*DM/BN, MT/BM), 256, GEMM_SMEM>>>(xh, wqh, wql,
                                                          qkvh, nullptr, MT, 3*DM, DM);
    attn_hmma<<<dim3(S_/64, B_*NH), 128, ATTN_SMEM>>>(qkvh, ah);
    gemm_fp16x2<<<dim3(DM/BN, MT/BM), 256, GEMM_SMEM>>>(ah, woh, wol,
                                                        nullptr, out, MT, DM, DM);
}

// round 9
// speedup vs baseline: 2.4828x; 1.6199x over previous
#include <cuda_runtime.h>
#include <cuda_fp16.h>
#include <math.h>
#include <stdint.h>

#define B_   2
#define S_   2048
#define DM   1024
#define NH   16
#define DH   64
#define WIN  256
#define SCALEF 0.125f
#define MT   (B_*S_)

// ---------------- scratch (__device__ globals; no allocs allowed) ----------
__device__ __half g_xh[(size_t)MT * DM];
__device__ __half g_wqT[(size_t)3*DM*DM];
__device__ __half g_woT[(size_t)DM*DM];
__device__ __half g_qkvh[(size_t)MT*3*DM];
__device__ __half g_ah[(size_t)MT*DM];

// ---------------- helpers ---------------------------------------------------
__device__ __forceinline__ uint32_t s2u(const void* p){
    uint32_t a;
    asm("{ .reg .u64 t; cvta.to.shared.u64 t, %1; cvt.u32.u64 %0, t; }":"=r"(a):"l"(p));
    return a;
}
__device__ __forceinline__ void cp16(uint32_t dst, const void* src){
    asm volatile("cp.async.cg.shared.global [%0], [%1], 16;"::"r"(dst),"l"(src));
}
__device__ __forceinline__ void ldsm_x4(uint32_t& r0,uint32_t& r1,uint32_t& r2,uint32_t& r3,uint32_t addr){
    asm volatile("ldmatrix.sync.aligned.m8n8.x4.shared.b16 {%0,%1,%2,%3}, [%4];"
        : "=r"(r0),"=r"(r1),"=r"(r2),"=r"(r3) : "r"(addr));
}
__device__ __forceinline__ void ldsm_x4t(uint32_t& r0,uint32_t& r1,uint32_t& r2,uint32_t& r3,uint32_t addr){
    asm volatile("ldmatrix.sync.aligned.m8n8.x4.trans.shared.b16 {%0,%1,%2,%3}, [%4];"
        : "=r"(r0),"=r"(r1),"=r"(r2),"=r"(r3) : "r"(addr));
}
__device__ __forceinline__ void mma16816(float* c, uint32_t a0,uint32_t a1,uint32_t a2,uint32_t a3,
                                         uint32_t b0,uint32_t b1){
    asm volatile("mma.sync.aligned.m16n8k16.row.col.f32.f16.f16.f32 "
        "{%0,%1,%2,%3}, {%4,%5,%6,%7}, {%8,%9}, {%0,%1,%2,%3};"
        : "+f"(c[0]),"+f"(c[1]),"+f"(c[2]),"+f"(c[3])
        : "r"(a0),"r"(a1),"r"(a2),"r"(a3),"r"(b0),"r"(b1));
}
__device__ __forceinline__ uint32_t packh2(float x, float y){
    __half2 h = __floats2half2_rn(x, y);
    return *(uint32_t*)&h;
}

// ---------------- prep kernels ---------------------------------------------
__global__ __launch_bounds__(256) void fhalf(const float* __restrict__ in,
                                             __half* __restrict__ hi, int n)
{
    int i = (blockIdx.x*256 + threadIdx.x)*4;
    if (i >= n) return;
    float4 v = *(const float4*)(in + i);
    *(__half2*)(hi + i)     = __floats2half2_rn(v.x, v.y);
    *(__half2*)(hi + i + 2) = __floats2half2_rn(v.z, v.w);
}

// W [K,N] row-major -> transposed fp16 Th [N,K]
__global__ __launch_bounds__(256) void thalf(const float* __restrict__ W,
                                             __half* __restrict__ Th, int K, int N)
{
    __shared__ float t[32][33];
    int n0 = blockIdx.x*32, k0 = blockIdx.y*32;
    int tx = threadIdx.x & 31, ty = threadIdx.x >> 5;  // 32x8
#pragma unroll
    for (int i = 0; i < 32; i += 8)
        t[ty+i][tx] = W[(size_t)(k0+ty+i)*N + n0+tx];
    __syncthreads();
#pragma unroll
    for (int i = 0; i < 32; i += 8)
        Th[(size_t)(n0+ty+i)*K + k0+tx] = __float2half_rn(t[tx][ty+i]);
}

// ---------------- pure fp16 HMMA GEMM ---------------------------------------
// C = A@B^T.  A [M,K] fp16, B [N,K] fp16.  Output fp16 (Ch) or fp32 (Cf).
#define BM 64
#define BN 128
#define BK 32
#define ROWB 80
#define OFF_A 0
#define OFF_B (BM*ROWB)
#define GSTAGE_BYTES ((BM+BN)*ROWB)          // 15360
#define GEMM_SMEM (3*GSTAGE_BYTES)           // 46080

__global__ __launch_bounds__(256, 2) void gemm_fp16(
    const __half* __restrict__ Ah, const __half* __restrict__ Bh,
    __half* __restrict__ Ch, float* __restrict__ Cf, int M, int N, int K)
{
    extern __shared__ char smraw[];
    const uint32_t sb = s2u(smraw);
    const int tid = threadIdx.x, lane = tid & 31, wid = tid >> 5;
    const int row0 = blockIdx.y * BM, col0 = blockIdx.x * BN;
    const int wm = (wid & 1) * 32;
    const int wn = (wid >> 1) * 32;
    const int nch = K / BK;

    const __half* pA = Ah + (size_t)row0 * K;
    const __half* pB = Bh + (size_t)col0 * K;

    const int lr = tid >> 2;
    const int lq = tid & 3;

    float acc[2][4][4];
#pragma unroll
    for (int f = 0; f < 2; f++)
#pragma unroll
        for (int j = 0; j < 4; j++)
#pragma unroll
            for (int i = 0; i < 4; i++) acc[f][j][i] = 0.f;

#define LOAD_STAGE(s_, c_)                                              \
    {                                                                   \
        uint32_t base_ = sb + (s_) * GSTAGE_BYTES;                      \
        size_t kof_ = (size_t)(c_) * BK;                                \
        uint32_t d_ = base_ + lr * ROWB + lq * 16;                      \
        size_t g_ = (size_t)lr * K + kof_ + lq * 8;                     \
        size_t g2_ = (size_t)(lr + 64) * K + kof_ + lq * 8;             \
        cp16(d_ + OFF_A, pA + g_);                                      \
        cp16(d_ + OFF_B, pB + g_);                                      \
        cp16(d_ + OFF_B + 64*ROWB, pB + g2_);                           \
    }

    LOAD_STAGE(0, 0);
    asm volatile("cp.async.commit_group;");
    LOAD_STAGE(1, 1);
    asm volatile("cp.async.commit_group;");

    for (int c = 0; c < nch; c++){
        asm volatile("cp.async.wait_group 1;");
        __syncthreads();

        if (c + 2 < nch){
            const int s2 = (c + 2) % 3;
            LOAD_STAGE(s2, c + 2);
        }
        asm volatile("cp.async.commit_group;");

        const uint32_t base = sb + (c % 3) * GSTAGE_BYTES;
#pragma unroll
        for (int ks = 0; ks < 2; ks++){
            const uint32_t kcol = (ks * 16 + (lane >> 4) * 8) * 2;
            uint32_t a[2][4], b[2][4];
#pragma unroll
            for (int f = 0; f < 2; f++){
                uint32_t ad = (wm + f * 16 + (lane & 15)) * ROWB + kcol;
                ldsm_x4(a[f][0], a[f][1], a[f][2], a[f][3], base + OFF_A + ad);
            }
#pragma unroll
            for (int g = 0; g < 2; g++){
                uint32_t bd = (wn + g * 16 + (lane & 15)) * ROWB + kcol;
                ldsm_x4(b[g][0], b[g][1], b[g][2], b[g][3], base + OFF_B + bd);
            }
#pragma unroll
            for (int f = 0; f < 2; f++)
#pragma unroll
                for (int j = 0; j < 4; j++){
                    const int g = j >> 1, o = j & 1;
                    mma16816(acc[f][j], a[f][0], a[f][1], a[f][2], a[f][3],
                             b[g][o], b[g][o + 2]);
                }
        }
    }

#pragma unroll
    for (int f = 0; f < 2; f++){
        const int row = row0 + wm + f * 16 + (lane >> 2);
#pragma unroll
        for (int j = 0; j < 4; j++){
            const int col = col0 + wn + j * 8 + (lane & 3) * 2;
            if (Cf){
                *(float2*)(Cf + (size_t)row * N + col)       = make_float2(acc[f][j][0], acc[f][j][1]);
                *(float2*)(Cf + (size_t)(row + 8) * N + col) = make_float2(acc[f][j][2], acc[f][j][3]);
            } else {
                *(uint32_t*)(Ch + (size_t)row * N + col)       = packh2(acc[f][j][0], acc[f][j][1]);
                *(uint32_t*)(Ch + (size_t)(row + 8) * N + col) = packh2(acc[f][j][2], acc[f][j][3]);
            }
        }
    }
}

// ---------------- fp16 HMMA sliding-window flash attention -------------------
#define RWB 144
#define AQ 0
#define AK (64*RWB)
#define AV (2*64*RWB)
#define ATTN_SMEM (3*64*RWB)    // 27648

__global__ __launch_bounds__(128) void attn_hmma(
    const __half* __restrict__ qkv, __half* __restrict__ oh)
{
    extern __shared__ char smc[];
    const uint32_t sb = s2u(smc);
    const int tid = threadIdx.x, lane = tid & 31, wid = tid >> 5;
    const int qt = blockIdx.x, bhid = blockIdx.y;
    const int b = bhid >> 4, h = bhid & 15;
    const int qs = qt * 64;
    const int wm = wid * 16;
    const size_t tok0 = (size_t)b * S_;

    {
        const __half* qb = qkv + (tok0 + qs) * 3072 + h * 64;
        for (int i = tid; i < 512; i += 128){
            int r = i >> 3, q = i & 7;
            *(uint4*)(smc + AQ + r*RWB + q*16) = *(const uint4*)(qb + (size_t)r*3072 + q*8);
        }
    }
    __syncthreads();

    uint32_t aq[4][4];
#pragma unroll
    for (int ks = 0; ks < 4; ks++){
        uint32_t ad = (uint32_t)((wm + (lane & 15)) * RWB + (ks*16 + (lane >> 4)*8) * 2);
        ldsm_x4(aq[ks][0], aq[ks][1], aq[ks][2], aq[ks][3], sb + AQ + ad);
    }

    float oacc[8][4];
#pragma unroll
    for (int f = 0; f < 8; f++)
#pragma unroll
        for (int e = 0; e < 4; e++) oacc[f][e] = 0.f;
    float m0 = -1e30f, m1 = -1e30f, l0 = 0.f, l1 = 0.f;

    const int ilo = qs + wm + (lane >> 2);
    const int ihi = ilo + 8;

    const int js = qs - (WIN - 1);
    const int t0 = js > 0 ? (js >> 6) : 0;

    for (int kt = t0; kt <= qt; kt++){
        const int jb = kt * 64;
        __syncthreads();
        for (int i = tid; i < 512; i += 128){
            int r = i >> 3, q = i & 7;
            size_t g = (tok0 + jb + r) * 3072 + h*64 + q*8;
            uint32_t so = r*RWB + q*16;
            *(uint4*)(smc + AK + so) = *(const uint4*)(qkv + g + 1024);
            *(uint4*)(smc + AV + so) = *(const uint4*)(qkv + g + 2048);
        }
        __syncthreads();

        float sacc[8][4];
#pragma unroll
        for (int f = 0; f < 8; f++)
#pragma unroll
            for (int e = 0; e < 4; e++) sacc[f][e] = 0.f;

#pragma unroll
        for (int g = 0; g < 4; g++){
#pragma unroll
            for (int ks = 0; ks < 4; ks++){
                uint32_t bd = (uint32_t)((g*16 + (lane & 15)) * RWB + (ks*16 + (lane >> 4)*8) * 2);
                uint32_t k0,k1,k2,k3;
                ldsm_x4(k0,k1,k2,k3, sb + AK + bd);
                mma16816(sacc[2*g],   aq[ks][0],aq[ks][1],aq[ks][2],aq[ks][3], k0, k2);
                mma16816(sacc[2*g+1], aq[ks][0],aq[ks][1],aq[ks][2],aq[ks][3], k1, k3);
            }
        }

        float mx0 = -1e30f, mx1 = -1e30f;
#pragma unroll
        for (int f = 0; f < 8; f++){
            int c0 = jb + f*8 + 2*(lane & 3);
            int c1 = c0 + 1;
            float s0 = sacc[f][0]*SCALEF, s1 = sacc[f][1]*SCALEF;
            float s2 = sacc[f][2]*SCALEF, s3 = sacc[f][3]*SCALEF;
            sacc[f][0] = (c0 <= ilo && c0 > ilo - WIN) ? s0 : -1e30f;
            sacc[f][1] = (c1 <= ilo && c1 > ilo - WIN) ? s1 : -1e30f;
            sacc[f][2] = (c0 <= ihi && c0 > ihi - WIN) ? s2 : -1e30f;
            sacc[f][3] = (c1 <= ihi && c1 > ihi - WIN) ? s3 : -1e30f;
            mx0 = fmaxf(mx0, fmaxf(sacc[f][0], sacc[f][1]));
            mx1 = fmaxf(mx1, fmaxf(sacc[f][2], sacc[f][3]));
        }
        mx0 = fmaxf(mx0, __shfl_xor_sync(0xffffffffu, mx0, 1));
        mx0 = fmaxf(mx0, __shfl_xor_sync(0xffffffffu, mx0, 2));
        mx1 = fmaxf(mx1, __shfl_xor_sync(0xffffffffu, mx1, 1));
        mx1 = fmaxf(mx1, __shfl_xor_sync(0xffffffffu, mx1, 2));
        float mn0 = fmaxf(m0, mx0), mn1 = fmaxf(m1, mx1);
        float rc0 = __expf(m0 - mn0), rc1 = __expf(m1 - mn1);
        float rs0 = 0.f, rs1 = 0.f;
#pragma unroll
        for (int f = 0; f < 8; f++){
            sacc[f][0] = __expf(sacc[f][0] - mn0);
            sacc[f][1] = __expf(sacc[f][1] - mn0);
            sacc[f][2] = __expf(sacc[f][2] - mn1);
            sacc[f][3] = __expf(sacc[f][3] - mn1);
            rs0 += sacc[f][0] + sacc[f][1];
            rs1 += sacc[f][2] + sacc[f][3];
        }
        rs0 += __shfl_xor_sync(0xffffffffu, rs0, 1);
        rs0 += __shfl_xor_sync(0xffffffffu, rs0, 2);
        rs1 += __shfl_xor_sync(0xffffffffu, rs1, 1);
        rs1 += __shfl_xor_sync(0xffffffffu, rs1, 2);
        l0 = l0 * rc0 + rs0;  l1 = l1 * rc1 + rs1;
        m0 = mn0;  m1 = mn1;
#pragma unroll
        for (int f = 0; f < 8; f++){
            oacc[f][0] *= rc0; oacc[f][1] *= rc0;
            oacc[f][2] *= rc1; oacc[f][3] *= rc1;
        }

#pragma unroll
        for (int kk = 0; kk < 4; kk++){
            uint32_t pa[4];
            pa[0] = packh2(sacc[2*kk][0],   sacc[2*kk][1]);
            pa[1] = packh2(sacc[2*kk][2],   sacc[2*kk][3]);
            pa[2] = packh2(sacc[2*kk+1][0], sacc[2*kk+1][1]);
            pa[3] = packh2(sacc[2*kk+1][2], sacc[2*kk+1][3]);
#pragma unroll
            for (int j2 = 0; j2 < 4; j2++){
                uint32_t vd = (uint32_t)((kk*16 + ((lane >> 3) & 1)*8 + (lane & 7)) * RWB
                                         + (j2*16 + (lane >> 4)*8) * 2);
                uint32_t v0,v1,v2,v3;
                ldsm_x4t(v0,v1,v2,v3, sb + AV + vd);
                mma16816(oacc[2*j2],   pa[0],pa[1],pa[2],pa[3], v0, v1);
                mma16816(oacc[2*j2+1], pa[0],pa[1],pa[2],pa[3], v2, v3);
            }
        }
    }

    float il0 = 1.f / l0, il1 = 1.f / l1;
    const int col = h*64 + 2*(lane & 3);
    size_t rowlo = (tok0 + ilo) * DM;
    size_t rowhi = (tok0 + ihi) * DM;
#pragma unroll
    for (int f = 0; f < 8; f++){
        *(uint32_t*)(oh + rowlo + col + f*8) = packh2(oacc[f][0]*il0, oacc[f][1]*il0);
        *(uint32_t*)(oh + rowhi + col + f*8) = packh2(oacc[f][2]*il1, oacc[f][3]*il1);
    }
}

// ---------------------------------------------------------------------------
extern "C" void kernel_launch(void* const* d_in, const int* in_sizes, int n_in,
                              void* d_out, int out_size)
{
    const float* x    = (const float*)d_in[0];
    const float* Wqkv = (const float*)d_in[1];
    const float* Wout = (const float*)d_in[2];
    float* out = (float*)d_out;

    __half *xh, *wq, *wo, *qkvh, *ah;
    cudaGetSymbolAddress((void**)&xh, g_xh);
    cudaGetSymbolAddress((void**)&wq, g_wqT);
    cudaGetSymbolAddress((void**)&wo, g_woT);
    cudaGetSymbolAddress((void**)&qkvh, g_qkvh);
    cudaGetSymbolAddress((void**)&ah, g_ah);

    cudaFuncSetAttribute(gemm_fp16, cudaFuncAttributeMaxDynamicSharedMemorySize, GEMM_SMEM);
    cudaFuncSetAttribute(attn_hmma, cudaFuncAttributeMaxDynamicSharedMemorySize, ATTN_SMEM);

    fhalf<<<(MT*DM/4 + 255)/256, 256>>>(x, xh, MT*DM);
    thalf<<<dim3(3*DM/32, DM/32), 256>>>(Wqkv, wq, DM, 3*DM);
    thalf<<<dim3(DM/32, DM/32), 256>>>(Wout, wo, DM, DM);
    gemm_fp16<<<dim3(3*DM/BN, MT/BM), 256, GEMM_SMEM>>>(xh, wq, qkvh, nullptr, MT, 3*DM, DM);
    attn_hmma<<<dim3(S_/64, B_*NH), 128, ATTN_SMEM>>>(qkvh, ah);
    gemm_fp16<<<dim3(DM/BN, MT/BM), 256, GEMM_SMEM>>>(ah, wo, nullptr, out, MT, DM, DM);
}